// round 2
// baseline (speedup 1.0000x reference)
#include <cuda_runtime.h>
#include <math.h>

// AllSetTransformerLayer on hypergraph, Q=1 specialization.
// Pipeline per block (v2e then e2v):
//   kq = K@Q  ->  alpha[n,h] = x[n].kq[h] ; xv = x @ V_cat (fused GEMM)
//   CSR build (hist/scan/scatter) over target segments
//   per-target warp: online segment softmax + weighted gather of xv rows
//   fused LN -> GEMM(W1) -> relu -> GEMM(W2) -> relu -> residual -> LN -> relu

#define IN_DIM 128
#define NHEAD 4
#define HDIM 32
#define MAX_ROWS 51200
#define MAX_E 1050000

__device__ float g_kq[NHEAD * IN_DIM];          // [h][c]
__device__ float g_alpha[MAX_ROWS * NHEAD];     // [n][h]
__device__ float g_xv[MAX_ROWS * IN_DIM];       // [n][d][h]  (float4 per (n,d))
__device__ float g_S1[MAX_ROWS * IN_DIM];       // aggregated pre-MLP features
__device__ int   g_cnt[MAX_ROWS + 1];
__device__ int   g_off[MAX_ROWS + 1];
__device__ int   g_cur[MAX_ROWS + 1];
__device__ int   g_csr[MAX_E];

__device__ __forceinline__ float warp_sum(float v) {
    #pragma unroll
    for (int off = 16; off; off >>= 1) v += __shfl_xor_sync(0xffffffffu, v, off);
    return v;
}

// ---------------------------------------------------------------------------
// kq[h][c] = sum_d K[h,c,d] * Q[h,0,d]
__global__ void kq_kernel(const float* __restrict__ K, const float* __restrict__ Q) {
    int tid = threadIdx.x;           // 512 threads: h = tid>>7, c = tid&127
    int h = tid >> 7, c = tid & 127;
    float s = 0.f;
    #pragma unroll
    for (int d = 0; d < HDIM; d++)
        s += K[h * (IN_DIM * HDIM) + c * HDIM + d] * Q[h * HDIM + d];
    g_kq[h * IN_DIM + c] = s;
}

// ---------------------------------------------------------------------------
// xv[n][d][h] = sum_c x[n,c] * V[h,c,d] ; alpha[n,h] = sum_c x[n,c]*kq[h,c]
// 128 threads, 32 rows per CTA. smem: ws 64KB + xs 16KB.
__global__ void gemm_xv_alpha(const float* __restrict__ x,
                              const float* __restrict__ V, int nrows) {
    extern __shared__ float sm[];
    float* ws = sm;            // [c][j] j = h*32+d, 128x128
    float* xs = sm + 16384;    // [r][c] 32x128
    int tid = threadIdx.x;
    int row0 = blockIdx.x * 32;

    for (int idx = tid; idx < 16384; idx += 128) {
        int c = idx >> 7, j = idx & 127;
        ws[idx] = V[(j >> 5) * (IN_DIM * HDIM) + c * HDIM + (j & 31)];
    }
    for (int idx = tid; idx < 4096; idx += 128) {
        int r = idx >> 7, c = idx & 127;
        int row = row0 + r;
        xs[idx] = (row < nrows) ? x[(size_t)row * IN_DIM + c] : 0.f;
    }
    __syncthreads();

    int tx = tid & 15, ty = tid >> 4;   // thread tile: 4 rows x 8 cols
    float acc[4][8];
    #pragma unroll
    for (int i = 0; i < 4; i++)
        #pragma unroll
        for (int j = 0; j < 8; j++) acc[i][j] = 0.f;

    for (int c = 0; c < 128; c++) {
        float xr[4];
        #pragma unroll
        for (int i = 0; i < 4; i++) xr[i] = xs[(ty * 4 + i) * 128 + c];
        float4 w0 = *(const float4*)&ws[c * 128 + tx * 8];
        float4 w1 = *(const float4*)&ws[c * 128 + tx * 8 + 4];
        float wv[8] = {w0.x, w0.y, w0.z, w0.w, w1.x, w1.y, w1.z, w1.w};
        #pragma unroll
        for (int i = 0; i < 4; i++)
            #pragma unroll
            for (int j = 0; j < 8; j++) acc[i][j] += xr[i] * wv[j];
    }

    #pragma unroll
    for (int i = 0; i < 4; i++) {
        int row = row0 + ty * 4 + i;
        if (row < nrows) {
            #pragma unroll
            for (int j = 0; j < 8; j++) {
                int col = tx * 8 + j;                 // col = h*32 + d
                // store layout [n][d][h] for float4 edge loads
                g_xv[(size_t)row * 128 + (col & 31) * 4 + (col >> 5)] = acc[i][j];
            }
        }
    }

    // alpha: 32 rows x 4 heads = 128 tasks, one per thread
    int r = tid >> 2, h = tid & 3;
    float s = 0.f;
    for (int c = 0; c < 128; c++) s += xs[r * 128 + c] * g_kq[h * IN_DIM + c];
    int row = row0 + r;
    if (row < nrows) g_alpha[(size_t)row * 4 + h] = s;
}

// ---------------------------------------------------------------------------
__global__ void clear_kernel(int n) {
    int i = blockIdx.x * blockDim.x + threadIdx.x;
    if (i < n) g_cnt[i] = 0;
}

__global__ void hist_kernel(const int* __restrict__ tgt, int E) {
    for (int e = blockIdx.x * blockDim.x + threadIdx.x; e < E;
         e += gridDim.x * blockDim.x)
        atomicAdd(&g_cnt[tgt[e]], 1);
}

// single-block exclusive scan of g_cnt[0..n) -> g_off, g_cur; g_off[n]=total
__global__ void scan_kernel(int n) {
    __shared__ int sh[1024];
    __shared__ int carry_s;
    int tid = threadIdx.x;
    if (tid == 0) carry_s = 0;
    __syncthreads();
    for (int base = 0; base < n; base += 1024) {
        int i = base + tid;
        int v = (i < n) ? g_cnt[i] : 0;
        sh[tid] = v;
        __syncthreads();
        for (int off = 1; off < 1024; off <<= 1) {
            int t = (tid >= off) ? sh[tid - off] : 0;
            __syncthreads();
            sh[tid] += t;
            __syncthreads();
        }
        int carry = carry_s;
        int excl = carry + sh[tid] - v;
        if (i < n) { g_off[i] = excl; g_cur[i] = excl; }
        __syncthreads();
        if (tid == 1023) carry_s = carry + sh[1023];
        __syncthreads();
    }
    if (tid == 0) g_off[n] = carry_s;
}

__global__ void scatter_kernel(const int* __restrict__ tgt, int E) {
    for (int e = blockIdx.x * blockDim.x + threadIdx.x; e < E;
         e += gridDim.x * blockDim.x) {
        int p = atomicAdd(&g_cur[tgt[e]], 1);
        g_csr[p] = e;
    }
}

// ---------------------------------------------------------------------------
// One warp per target segment: online softmax over edges, then weighted
// accumulation of xv rows. out row = agg + Qbias.
__global__ void segagg_kernel(const int* __restrict__ src,
                              const float* __restrict__ qbias, int n_tgt) {
    int gw = (int)((blockIdx.x * blockDim.x + threadIdx.x) >> 5);
    int lane = threadIdx.x & 31;
    if (gw >= n_tgt) return;
    int start = g_off[gw], end = g_off[gw + 1];
    float* outrow = &g_S1[(size_t)gw * 128];

    if (end == start) {   // empty segment: aggregation is 0, keep bias
        #pragma unroll
        for (int k = 0; k < 4; k++) outrow[k * 32 + lane] = qbias[k * 32 + lane];
        return;
    }

    float m[4], s[4];
    #pragma unroll
    for (int k = 0; k < 4; k++) { m[k] = -1e30f; s[k] = 0.f; }

    for (int i = start + lane; i < end; i += 32) {
        int e = g_csr[i];
        int sn = src[e];
        float4 a4 = *(const float4*)&g_alpha[(size_t)sn * 4];
        float a[4] = {a4.x, a4.y, a4.z, a4.w};
        #pragma unroll
        for (int k = 0; k < 4; k++) {
            if (a[k] > m[k]) { s[k] = s[k] * __expf(m[k] - a[k]) + 1.f; m[k] = a[k]; }
            else             { s[k] += __expf(a[k] - m[k]); }
        }
    }
    #pragma unroll
    for (int off = 16; off; off >>= 1) {
        #pragma unroll
        for (int k = 0; k < 4; k++) {
            float mo = __shfl_xor_sync(0xffffffffu, m[k], off);
            float so = __shfl_xor_sync(0xffffffffu, s[k], off);
            float mn = fmaxf(m[k], mo);
            s[k] = s[k] * __expf(m[k] - mn) + so * __expf(mo - mn);
            m[k] = mn;
        }
    }
    float inv[4];
    #pragma unroll
    for (int k = 0; k < 4; k++) inv[k] = 1.0f / s[k];

    float acc[4] = {0.f, 0.f, 0.f, 0.f};
    for (int i = start; i < end; i++) {
        int e = g_csr[i];
        int sn = src[e];
        float4 a4 = *(const float4*)&g_alpha[(size_t)sn * 4];
        float4 v4 = *(const float4*)&g_xv[(size_t)sn * 128 + lane * 4];
        acc[0] += __expf(a4.x - m[0]) * inv[0] * v4.x;
        acc[1] += __expf(a4.y - m[1]) * inv[1] * v4.y;
        acc[2] += __expf(a4.z - m[2]) * inv[2] * v4.z;
        acc[3] += __expf(a4.w - m[3]) * inv[3] * v4.w;
    }
    #pragma unroll
    for (int k = 0; k < 4; k++)
        outrow[k * 32 + lane] = acc[k] + qbias[k * 32 + lane];
}

// ---------------------------------------------------------------------------
// Fused LN0 -> relu(h@W1) -> relu(t@W2) -> residual -> LN1 -> relu -> out
// 256 threads, 64 rows/CTA. smem: h 32KB + t 32KB + w 64KB = 128KB.
__global__ void mlp_kernel(const float* __restrict__ g0, const float* __restrict__ b0,
                           const float* __restrict__ W1, const float* __restrict__ W2,
                           const float* __restrict__ g1, const float* __restrict__ b1,
                           float* __restrict__ out, int nrows) {
    extern __shared__ float sm[];
    float* sh_h = sm;            // 64x128
    float* sh_t = sm + 8192;     // 64x128
    float* sh_w = sm + 16384;    // 128x128
    int tid = threadIdx.x;
    int row0 = blockIdx.x * 64;

    for (int idx = tid; idx < 8192; idx += 256) {
        int r = idx >> 7, c = idx & 127;
        int row = row0 + r;
        sh_h[idx] = (row < nrows) ? g_S1[(size_t)row * 128 + c] : 0.f;
    }
    for (int idx = tid; idx < 16384; idx += 256) sh_w[idx] = W1[idx];
    __syncthreads();

    int wid = tid >> 5, lane = tid & 31;
    // LN0 in place
    for (int r = wid; r < 64; r += 8) {
        float v[4];
        #pragma unroll
        for (int k = 0; k < 4; k++) v[k] = sh_h[r * 128 + lane + 32 * k];
        float mean = warp_sum(v[0] + v[1] + v[2] + v[3]) * (1.f / 128.f);
        float d[4], sq = 0.f;
        #pragma unroll
        for (int k = 0; k < 4; k++) { d[k] = v[k] - mean; sq += d[k] * d[k]; }
        float var = warp_sum(sq) * (1.f / 128.f);
        float rstd = rsqrtf(var + 1e-5f);
        #pragma unroll
        for (int k = 0; k < 4; k++)
            sh_h[r * 128 + lane + 32 * k] =
                d[k] * rstd * g0[lane + 32 * k] + b0[lane + 32 * k];
    }
    __syncthreads();

    int tx = tid & 15, ty = tid >> 4;
    float acc[4][8];
    #pragma unroll
    for (int i = 0; i < 4; i++)
        #pragma unroll
        for (int j = 0; j < 8; j++) acc[i][j] = 0.f;

    for (int c = 0; c < 128; c++) {
        float xr[4];
        #pragma unroll
        for (int i = 0; i < 4; i++) xr[i] = sh_h[(ty * 4 + i) * 128 + c];
        float4 w0 = *(const float4*)&sh_w[c * 128 + tx * 8];
        float4 w1 = *(const float4*)&sh_w[c * 128 + tx * 8 + 4];
        float wv[8] = {w0.x, w0.y, w0.z, w0.w, w1.x, w1.y, w1.z, w1.w};
        #pragma unroll
        for (int i = 0; i < 4; i++)
            #pragma unroll
            for (int j = 0; j < 8; j++) acc[i][j] += xr[i] * wv[j];
    }
    #pragma unroll
    for (int i = 0; i < 4; i++)
        #pragma unroll
        for (int j = 0; j < 8; j++)
            sh_t[(ty * 4 + i) * 128 + tx * 8 + j] = fmaxf(acc[i][j], 0.f);
    __syncthreads();

    for (int idx = tid; idx < 16384; idx += 256) sh_w[idx] = W2[idx];
    __syncthreads();

    #pragma unroll
    for (int i = 0; i < 4; i++)
        #pragma unroll
        for (int j = 0; j < 8; j++) acc[i][j] = 0.f;
    for (int c = 0; c < 128; c++) {
        float xr[4];
        #pragma unroll
        for (int i = 0; i < 4; i++) xr[i] = sh_t[(ty * 4 + i) * 128 + c];
        float4 w0 = *(const float4*)&sh_w[c * 128 + tx * 8];
        float4 w1 = *(const float4*)&sh_w[c * 128 + tx * 8 + 4];
        float wv[8] = {w0.x, w0.y, w0.z, w0.w, w1.x, w1.y, w1.z, w1.w};
        #pragma unroll
        for (int i = 0; i < 4; i++)
            #pragma unroll
            for (int j = 0; j < 8; j++) acc[i][j] += xr[i] * wv[j];
    }
    __syncthreads();   // all sh_t reads done before overwrite
    #pragma unroll
    for (int i = 0; i < 4; i++)
        #pragma unroll
        for (int j = 0; j < 8; j++) {
            int r = ty * 4 + i, col = tx * 8 + j;
            sh_t[r * 128 + col] = sh_h[r * 128 + col] + fmaxf(acc[i][j], 0.f);
        }
    __syncthreads();

    // LN1 + relu + store
    for (int r = wid; r < 64; r += 8) {
        float v[4];
        #pragma unroll
        for (int k = 0; k < 4; k++) v[k] = sh_t[r * 128 + lane + 32 * k];
        float mean = warp_sum(v[0] + v[1] + v[2] + v[3]) * (1.f / 128.f);
        float d[4], sq = 0.f;
        #pragma unroll
        for (int k = 0; k < 4; k++) { d[k] = v[k] - mean; sq += d[k] * d[k]; }
        float var = warp_sum(sq) * (1.f / 128.f);
        float rstd = rsqrtf(var + 1e-5f);
        int row = row0 + r;
        if (row < nrows) {
            #pragma unroll
            for (int k = 0; k < 4; k++)
                out[(size_t)row * 128 + lane + 32 * k] =
                    fmaxf(d[k] * rstd * g1[lane + 32 * k] + b1[lane + 32 * k], 0.f);
        }
    }
}

// ---------------------------------------------------------------------------
extern "C" void kernel_launch(void* const* d_in, const int* in_sizes, int n_in,
                              void* d_out, int out_size) {
    const int N = in_sizes[0] / IN_DIM;
    const int E = in_sizes[1];
    const int M = out_size / IN_DIM - N;

    // weights start after x_0, node_idx, hedge_idx (+ optional 2 scalars)
    const int wi = n_in - 18;
    const float* x0 = (const float*)d_in[0];
    const int* node_idx  = (const int*)d_in[1];
    const int* hedge_idx = (const int*)d_in[2];
    const float* w[18];
    for (int i = 0; i < 18; i++) w[i] = (const float*)d_in[wi + i];
    // w[0..8]:  v2e K,Q,V,ln0_g,ln0_b,W1,W2,ln1_g,ln1_b
    // w[9..17]: e2v K,Q,V,ln0_g,ln0_b,W1,W2,ln1_g,ln1_b

    float* out = (float*)d_out;            // x_0_out [N,128]
    float* x1  = out + (size_t)N * IN_DIM; // x_1     [M,128]

    cudaFuncSetAttribute(gemm_xv_alpha,
                         cudaFuncAttributeMaxDynamicSharedMemorySize, 81920);
    cudaFuncSetAttribute(mlp_kernel,
                         cudaFuncAttributeMaxDynamicSharedMemorySize, 131072);

    const int histGrid = (E + 255) / 256;

    // ---- v2e: targets = hyperedges (M), sources = nodes ----
    kq_kernel<<<1, 512>>>(w[0], w[1]);
    gemm_xv_alpha<<<(N + 31) / 32, 128, 81920>>>(x0, w[2], N);
    clear_kernel<<<(M + 256) / 256, 256>>>(M + 1);
    hist_kernel<<<histGrid, 256>>>(hedge_idx, E);
    scan_kernel<<<1, 1024>>>(M);
    scatter_kernel<<<histGrid, 256>>>(hedge_idx, E);
    segagg_kernel<<<(M + 7) / 8, 256>>>(node_idx, w[1], M);
    mlp_kernel<<<(M + 63) / 64, 256, 131072>>>(w[3], w[4], w[5], w[6], w[7], w[8],
                                               x1, M);

    // ---- e2v: targets = nodes (N), sources = hyperedges ----
    kq_kernel<<<1, 512>>>(w[9], w[10]);
    gemm_xv_alpha<<<(M + 31) / 32, 128, 81920>>>(x1, w[11], M);
    clear_kernel<<<(N + 256) / 256, 256>>>(N + 1);
    hist_kernel<<<histGrid, 256>>>(node_idx, E);
    scan_kernel<<<1, 1024>>>(N);
    scatter_kernel<<<histGrid, 256>>>(node_idx, E);
    segagg_kernel<<<(N + 7) / 8, 256>>>(hedge_idx, w[10], N);
    mlp_kernel<<<(N + 63) / 64, 256, 131072>>>(w[12], w[13], w[14], w[15], w[16],
                                               w[17], out, N);
}

// round 3
// speedup vs baseline: 1.9884x; 1.9884x over previous
#include <cuda_runtime.h>
#include <math.h>

#define IN_DIM 128
#define NHEAD 4
#define HDIM 32
#define MAX_ROWS 51200
#define MAX_E 1050000

__device__ __align__(16) float g_kq[NHEAD * IN_DIM];      // [h][c]
__device__ __align__(16) float g_alpha[MAX_ROWS * NHEAD]; // [n][h]
__device__ __align__(16) float g_xv[MAX_ROWS * IN_DIM];   // [n][d*4+h]
__device__ __align__(16) float g_S1[MAX_ROWS * IN_DIM];   // pre-MLP features
__device__ __align__(16) float g_ea[MAX_E * 4];           // per CSR slot: alpha4
__device__ int g_esrc[MAX_E];                             // per CSR slot: src idx
__device__ int g_cnt[MAX_ROWS + 1];
__device__ int g_off[MAX_ROWS + 1];
__device__ int g_cur[MAX_ROWS + 1];
__device__ int g_bsum[64];

__device__ __forceinline__ float warp_sum(float v) {
    #pragma unroll
    for (int off = 16; off; off >>= 1) v += __shfl_xor_sync(0xffffffffu, v, off);
    return v;
}

// ---------------------------------------------------------------------------
// kq[h][c] = sum_d K[h,c,d] * Q[h,0,d]
__global__ void kq_kernel(const float* __restrict__ K, const float* __restrict__ Q) {
    int tid = threadIdx.x;           // 512 threads: h = tid>>7, c = tid&127
    int h = tid >> 7, c = tid & 127;
    float s = 0.f;
    #pragma unroll
    for (int d = 0; d < HDIM; d++)
        s += K[h * (IN_DIM * HDIM) + c * HDIM + d] * Q[h * HDIM + d];
    g_kq[h * IN_DIM + c] = s;
}

// ---------------------------------------------------------------------------
// alpha[n,h] = x[n] . kq[h]. one warp per row.
__global__ void alpha_kernel(const float* __restrict__ x, int nrows) {
    __shared__ float kq_s[512];
    int tid = threadIdx.x;
    kq_s[tid] = g_kq[tid];
    kq_s[tid + 256] = g_kq[tid + 256];
    __syncthreads();
    int wid = tid >> 5, lane = tid & 31;
    int row = blockIdx.x * 8 + wid;
    if (row >= nrows) return;
    float4 xr = *(const float4*)&x[(size_t)row * 128 + lane * 4];
    float s[4];
    #pragma unroll
    for (int h = 0; h < 4; h++) {
        float4 k4 = *(const float4*)&kq_s[h * 128 + lane * 4];
        s[h] = xr.x * k4.x + xr.y * k4.y + xr.z * k4.z + xr.w * k4.w;
        s[h] = warp_sum(s[h]);
    }
    if (lane == 0)
        *(float4*)&g_alpha[(size_t)row * 4] = make_float4(s[0], s[1], s[2], s[3]);
}

// ---------------------------------------------------------------------------
// xv[n][d*4+h] = sum_c x[n,c] * V[h,c,d]. 128 rows/CTA, 256 thr, 8x8 tiles.
__global__ void __launch_bounds__(256, 1)
gemm_xv(const float* __restrict__ x, const float* __restrict__ V, int nrows) {
    extern __shared__ float sm[];
    float* ws = sm;            // [c][d*4+h] permuted, 128x128
    float* xs = sm + 16384;    // [r][c], 128x128
    int tid = threadIdx.x;
    int row0 = blockIdx.x * 128;

    for (int idx = tid; idx < 16384; idx += 256) {   // V linear: h,c,d
        int h = idx >> 12, c = (idx >> 5) & 127, d = idx & 31;
        ws[c * 128 + d * 4 + h] = V[idx];
    }
    for (int idx = tid; idx < 4096; idx += 256) {    // 4096 float4s
        int r = idx >> 5, q = idx & 31;
        int row = row0 + r;
        float4 v = (row < nrows) ? *(const float4*)&x[(size_t)row * 128 + q * 4]
                                 : make_float4(0.f, 0.f, 0.f, 0.f);
        *(float4*)&xs[r * 128 + q * 4] = v;
    }
    __syncthreads();

    int tx = tid & 15, ty = tid >> 4;
    float acc[8][8];
    #pragma unroll
    for (int i = 0; i < 8; i++)
        #pragma unroll
        for (int j = 0; j < 8; j++) acc[i][j] = 0.f;

    for (int c = 0; c < 128; c++) {
        float xr[8];
        #pragma unroll
        for (int i = 0; i < 8; i++) xr[i] = xs[(ty * 8 + i) * 128 + c];
        float4 w0 = *(const float4*)&ws[c * 128 + tx * 8];
        float4 w1 = *(const float4*)&ws[c * 128 + tx * 8 + 4];
        float wv[8] = {w0.x, w0.y, w0.z, w0.w, w1.x, w1.y, w1.z, w1.w};
        #pragma unroll
        for (int i = 0; i < 8; i++)
            #pragma unroll
            for (int j = 0; j < 8; j++) acc[i][j] += xr[i] * wv[j];
    }
    #pragma unroll
    for (int i = 0; i < 8; i++) {
        int row = row0 + ty * 8 + i;
        if (row < nrows) {
            *(float4*)&g_xv[(size_t)row * 128 + tx * 8] =
                make_float4(acc[i][0], acc[i][1], acc[i][2], acc[i][3]);
            *(float4*)&g_xv[(size_t)row * 128 + tx * 8 + 4] =
                make_float4(acc[i][4], acc[i][5], acc[i][6], acc[i][7]);
        }
    }
}

// ---------------------------------------------------------------------------
__global__ void hist_kernel(const int* __restrict__ tgt, int E) {
    for (int e = blockIdx.x * blockDim.x + threadIdx.x; e < E;
         e += gridDim.x * blockDim.x)
        atomicAdd(&g_cnt[tgt[e]], 1);
}

__global__ void scan1(int n) {   // 1024 threads per block
    __shared__ int wsum[32];
    int tid = threadIdx.x, lane = tid & 31, wid = tid >> 5;
    int i = blockIdx.x * 1024 + tid;
    int v = (i < n) ? g_cnt[i] : 0;
    int x = v;
    #pragma unroll
    for (int o = 1; o < 32; o <<= 1) {
        int t = __shfl_up_sync(0xffffffffu, x, o);
        if (lane >= o) x += t;
    }
    if (lane == 31) wsum[wid] = x;
    __syncthreads();
    if (wid == 0) {
        int s = wsum[lane];
        #pragma unroll
        for (int o = 1; o < 32; o <<= 1) {
            int t = __shfl_up_sync(0xffffffffu, s, o);
            if (lane >= o) s += t;
        }
        wsum[lane] = s;
    }
    __syncthreads();
    int base = (wid > 0) ? wsum[wid - 1] : 0;
    if (i < n) g_off[i] = base + x - v;
    if (tid == 1023) g_bsum[blockIdx.x] = base + x;
}

__global__ void scan2(int nb, int n) {   // 32 threads
    int lane = threadIdx.x;
    int v0 = (lane < nb) ? g_bsum[lane] : 0;
    int v1 = (32 + lane < nb) ? g_bsum[32 + lane] : 0;
    int x0 = v0, x1 = v1;
    #pragma unroll
    for (int o = 1; o < 32; o <<= 1) {
        int t = __shfl_up_sync(0xffffffffu, x0, o);
        if (lane >= o) x0 += t;
    }
    int tot0 = __shfl_sync(0xffffffffu, x0, 31);
    #pragma unroll
    for (int o = 1; o < 32; o <<= 1) {
        int t = __shfl_up_sync(0xffffffffu, x1, o);
        if (lane >= o) x1 += t;
    }
    x1 += tot0;
    int tot = __shfl_sync(0xffffffffu, x1, 31);
    if (lane < nb) g_bsum[lane] = x0 - v0;
    if (32 + lane < nb) g_bsum[32 + lane] = x1 - v1;
    if (lane == 0) g_off[n] = tot;
}

__global__ void scan3(int n) {   // same grid as scan1
    int i = blockIdx.x * 1024 + threadIdx.x;
    if (i < n) {
        int o = g_off[i] + g_bsum[blockIdx.x];
        g_off[i] = o;
        g_cur[i] = o;
    }
}

// scatter with source resolution: write src idx + its alpha4 at CSR slot
__global__ void scatter_kernel(const int* __restrict__ tgt,
                               const int* __restrict__ src, int E) {
    for (int e = blockIdx.x * blockDim.x + threadIdx.x; e < E;
         e += gridDim.x * blockDim.x) {
        int t = tgt[e], sn = src[e];
        float4 a = *(const float4*)&g_alpha[(size_t)sn * 4];
        int p = atomicAdd(&g_cur[t], 1);
        g_esrc[p] = sn;
        *(float4*)&g_ea[(size_t)p * 4] = a;
    }
}

// ---------------------------------------------------------------------------
// One warp per target: pass1 coalesced online softmax over g_ea,
// pass2 shuffle-broadcast weights, one float4 gather per edge per lane.
__global__ void segagg_kernel(const float* __restrict__ qbias, int n_tgt) {
    int gw = (int)((blockIdx.x * blockDim.x + threadIdx.x) >> 5);
    int lane = threadIdx.x & 31;
    if (gw >= n_tgt) return;
    int start = g_off[gw], end = g_off[gw + 1];
    float* outrow = &g_S1[(size_t)gw * 128];

    if (end == start) {
        #pragma unroll
        for (int k = 0; k < 4; k++) outrow[k * 32 + lane] = qbias[k * 32 + lane];
        return;
    }

    float m[4], s[4];
    #pragma unroll
    for (int k = 0; k < 4; k++) { m[k] = -1e30f; s[k] = 0.f; }
    for (int i = start + lane; i < end; i += 32) {
        float4 a4 = *(const float4*)&g_ea[(size_t)i * 4];
        float a[4] = {a4.x, a4.y, a4.z, a4.w};
        #pragma unroll
        for (int k = 0; k < 4; k++) {
            if (a[k] > m[k]) { s[k] = s[k] * __expf(m[k] - a[k]) + 1.f; m[k] = a[k]; }
            else             { s[k] += __expf(a[k] - m[k]); }
        }
    }
    #pragma unroll
    for (int off = 16; off; off >>= 1) {
        #pragma unroll
        for (int k = 0; k < 4; k++) {
            float mo = __shfl_xor_sync(0xffffffffu, m[k], off);
            float so = __shfl_xor_sync(0xffffffffu, s[k], off);
            float mn = fmaxf(m[k], mo);
            s[k] = s[k] * __expf(m[k] - mn) + so * __expf(mo - mn);
            m[k] = mn;
        }
    }
    float inv[4];
    #pragma unroll
    for (int k = 0; k < 4; k++) inv[k] = 1.0f / s[k];

    float acc[4] = {0.f, 0.f, 0.f, 0.f};
    for (int i0 = start; i0 < end; i0 += 32) {
        int cnt = end - i0; if (cnt > 32) cnt = 32;
        int idx = 0;
        float w0 = 0.f, w1 = 0.f, w2 = 0.f, w3 = 0.f;
        if (lane < cnt) {
            idx = g_esrc[i0 + lane];
            float4 a4 = *(const float4*)&g_ea[(size_t)(i0 + lane) * 4];
            w0 = __expf(a4.x - m[0]) * inv[0];
            w1 = __expf(a4.y - m[1]) * inv[1];
            w2 = __expf(a4.z - m[2]) * inv[2];
            w3 = __expf(a4.w - m[3]) * inv[3];
        }
        for (int j = 0; j < cnt; j++) {
            int sn   = __shfl_sync(0xffffffffu, idx, j);
            float a0 = __shfl_sync(0xffffffffu, w0, j);
            float a1 = __shfl_sync(0xffffffffu, w1, j);
            float a2 = __shfl_sync(0xffffffffu, w2, j);
            float a3 = __shfl_sync(0xffffffffu, w3, j);
            float4 v = *(const float4*)&g_xv[(size_t)sn * 128 + lane * 4];
            acc[0] += a0 * v.x; acc[1] += a1 * v.y;
            acc[2] += a2 * v.z; acc[3] += a3 * v.w;
        }
    }
    #pragma unroll
    for (int k = 0; k < 4; k++)
        outrow[k * 32 + lane] = acc[k] + qbias[k * 32 + lane];
}

// ---------------------------------------------------------------------------
// LN0 -> relu(h@W1) -> relu(t@W2) -> residual -> LN1 -> relu. 128 rows/CTA.
__global__ void __launch_bounds__(256, 1)
mlp_kernel(const float* __restrict__ g0, const float* __restrict__ b0,
           const float* __restrict__ W1, const float* __restrict__ W2,
           const float* __restrict__ g1, const float* __restrict__ b1,
           float* __restrict__ out, int nrows) {
    extern __shared__ float sm[];
    float* sh_h = sm;            // 128x128
    float* sh_t = sm + 16384;    // 128x128
    float* sh_w = sm + 32768;    // 128x128
    int tid = threadIdx.x;
    int row0 = blockIdx.x * 128;
    int wid = tid >> 5, lane = tid & 31;

    for (int idx = tid; idx < 4096; idx += 256) {
        int r = idx >> 5, q = idx & 31;
        int row = row0 + r;
        float4 v = (row < nrows) ? *(const float4*)&g_S1[(size_t)row * 128 + q * 4]
                                 : make_float4(0.f, 0.f, 0.f, 0.f);
        *(float4*)&sh_h[r * 128 + q * 4] = v;
    }
    for (int idx = tid; idx < 4096; idx += 256)
        *(float4*)&sh_w[idx * 4] = *(const float4*)&W1[idx * 4];
    __syncthreads();

    float4 gA = *(const float4*)&g0[lane * 4];
    float4 bA = *(const float4*)&b0[lane * 4];
    for (int r = wid; r < 128; r += 8) {
        float4 v = *(float4*)&sh_h[r * 128 + lane * 4];
        float mean = warp_sum(v.x + v.y + v.z + v.w) * (1.f / 128.f);
        float dx = v.x - mean, dy = v.y - mean, dz = v.z - mean, dw = v.w - mean;
        float var = warp_sum(dx * dx + dy * dy + dz * dz + dw * dw) * (1.f / 128.f);
        float rstd = rsqrtf(var + 1e-5f);
        *(float4*)&sh_h[r * 128 + lane * 4] =
            make_float4(dx * rstd * gA.x + bA.x, dy * rstd * gA.y + bA.y,
                        dz * rstd * gA.z + bA.z, dw * rstd * gA.w + bA.w);
    }
    __syncthreads();

    int tx = tid & 15, ty = tid >> 4;
    float acc[8][8];
    #pragma unroll
    for (int i = 0; i < 8; i++)
        #pragma unroll
        for (int j = 0; j < 8; j++) acc[i][j] = 0.f;
    for (int c = 0; c < 128; c++) {
        float xr[8];
        #pragma unroll
        for (int i = 0; i < 8; i++) xr[i] = sh_h[(ty * 8 + i) * 128 + c];
        float4 w0 = *(const float4*)&sh_w[c * 128 + tx * 8];
        float4 w1 = *(const float4*)&sh_w[c * 128 + tx * 8 + 4];
        float wv[8] = {w0.x, w0.y, w0.z, w0.w, w1.x, w1.y, w1.z, w1.w};
        #pragma unroll
        for (int i = 0; i < 8; i++)
            #pragma unroll
            for (int j = 0; j < 8; j++) acc[i][j] += xr[i] * wv[j];
    }
    #pragma unroll
    for (int i = 0; i < 8; i++) {
        *(float4*)&sh_t[(ty * 8 + i) * 128 + tx * 8] =
            make_float4(fmaxf(acc[i][0], 0.f), fmaxf(acc[i][1], 0.f),
                        fmaxf(acc[i][2], 0.f), fmaxf(acc[i][3], 0.f));
        *(float4*)&sh_t[(ty * 8 + i) * 128 + tx * 8 + 4] =
            make_float4(fmaxf(acc[i][4], 0.f), fmaxf(acc[i][5], 0.f),
                        fmaxf(acc[i][6], 0.f), fmaxf(acc[i][7], 0.f));
    }
    __syncthreads();

    for (int idx = tid; idx < 4096; idx += 256)
        *(float4*)&sh_w[idx * 4] = *(const float4*)&W2[idx * 4];
    __syncthreads();

    #pragma unroll
    for (int i = 0; i < 8; i++)
        #pragma unroll
        for (int j = 0; j < 8; j++) acc[i][j] = 0.f;
    for (int c = 0; c < 128; c++) {
        float xr[8];
        #pragma unroll
        for (int i = 0; i < 8; i++) xr[i] = sh_t[(ty * 8 + i) * 128 + c];
        float4 w0 = *(const float4*)&sh_w[c * 128 + tx * 8];
        float4 w1 = *(const float4*)&sh_w[c * 128 + tx * 8 + 4];
        float wv[8] = {w0.x, w0.y, w0.z, w0.w, w1.x, w1.y, w1.z, w1.w};
        #pragma unroll
        for (int i = 0; i < 8; i++)
            #pragma unroll
            for (int j = 0; j < 8; j++) acc[i][j] += xr[i] * wv[j];
    }
    __syncthreads();
    #pragma unroll
    for (int i = 0; i < 8; i++) {
        int r = ty * 8 + i;
        float4 h0 = *(const float4*)&sh_h[r * 128 + tx * 8];
        float4 h1 = *(const float4*)&sh_h[r * 128 + tx * 8 + 4];
        *(float4*)&sh_t[r * 128 + tx * 8] =
            make_float4(h0.x + fmaxf(acc[i][0], 0.f), h0.y + fmaxf(acc[i][1], 0.f),
                        h0.z + fmaxf(acc[i][2], 0.f), h0.w + fmaxf(acc[i][3], 0.f));
        *(float4*)&sh_t[r * 128 + tx * 8 + 4] =
            make_float4(h1.x + fmaxf(acc[i][4], 0.f), h1.y + fmaxf(acc[i][5], 0.f),
                        h1.z + fmaxf(acc[i][6], 0.f), h1.w + fmaxf(acc[i][7], 0.f));
    }
    __syncthreads();

    float4 gB = *(const float4*)&g1[lane * 4];
    float4 bB = *(const float4*)&b1[lane * 4];
    for (int r = wid; r < 128; r += 8) {
        float4 v = *(float4*)&sh_t[r * 128 + lane * 4];
        float mean = warp_sum(v.x + v.y + v.z + v.w) * (1.f / 128.f);
        float dx = v.x - mean, dy = v.y - mean, dz = v.z - mean, dw = v.w - mean;
        float var = warp_sum(dx * dx + dy * dy + dz * dz + dw * dw) * (1.f / 128.f);
        float rstd = rsqrtf(var + 1e-5f);
        int row = row0 + r;
        if (row < nrows) {
            *(float4*)&out[(size_t)row * 128 + lane * 4] =
                make_float4(fmaxf(dx * rstd * gB.x + bB.x, 0.f),
                            fmaxf(dy * rstd * gB.y + bB.y, 0.f),
                            fmaxf(dz * rstd * gB.z + bB.z, 0.f),
                            fmaxf(dw * rstd * gB.w + bB.w, 0.f));
        }
    }
}

// ---------------------------------------------------------------------------
extern "C" void kernel_launch(void* const* d_in, const int* in_sizes, int n_in,
                              void* d_out, int out_size) {
    const int N = in_sizes[0] / IN_DIM;
    const int E = in_sizes[1];
    const int M = out_size / IN_DIM - N;

    const int wi = n_in - 18;
    const float* x0 = (const float*)d_in[0];
    const int* node_idx  = (const int*)d_in[1];
    const int* hedge_idx = (const int*)d_in[2];
    const float* w[18];
    for (int i = 0; i < 18; i++) w[i] = (const float*)d_in[wi + i];

    float* out = (float*)d_out;            // x_0_out [N,128]
    float* x1  = out + (size_t)N * IN_DIM; // x_1     [M,128]

    static int s_init = 0;
    if (!s_init) {
        cudaFuncSetAttribute(gemm_xv,
                             cudaFuncAttributeMaxDynamicSharedMemorySize, 131072);
        cudaFuncSetAttribute(mlp_kernel,
                             cudaFuncAttributeMaxDynamicSharedMemorySize, 196608);
        s_init = 1;
    }
    void* cnt_ptr;
    cudaGetSymbolAddress(&cnt_ptr, g_cnt);

    const int histGrid = (E + 255) / 256;

    // ---- v2e: targets = hyperedges (M), sources = nodes ----
    {
        int nb = (M + 1023) / 1024;
        kq_kernel<<<1, 512>>>(w[0], w[1]);
        gemm_xv<<<(N + 127) / 128, 256, 131072>>>(x0, w[2], N);
        alpha_kernel<<<(N + 7) / 8, 256>>>(x0, N);
        cudaMemsetAsync(cnt_ptr, 0, sizeof(int) * (M + 1), 0);
        hist_kernel<<<histGrid, 256>>>(hedge_idx, E);
        scan1<<<nb, 1024>>>(M);
        scan2<<<1, 32>>>(nb, M);
        scan3<<<nb, 1024>>>(M);
        scatter_kernel<<<histGrid, 256>>>(hedge_idx, node_idx, E);
        segagg_kernel<<<(M + 7) / 8, 256>>>(w[1], M);
        mlp_kernel<<<(M + 127) / 128, 256, 196608>>>(w[3], w[4], w[5], w[6], w[7],
                                                     w[8], x1, M);
    }
    // ---- e2v: targets = nodes (N), sources = hyperedges ----
    {
        int nb = (N + 1023) / 1024;
        kq_kernel<<<1, 512>>>(w[9], w[10]);
        gemm_xv<<<(M + 127) / 128, 256, 131072>>>(x1, w[11], M);
        alpha_kernel<<<(M + 7) / 8, 256>>>(x1, M);
        cudaMemsetAsync(cnt_ptr, 0, sizeof(int) * (N + 1), 0);
        hist_kernel<<<histGrid, 256>>>(node_idx, E);
        scan1<<<nb, 1024>>>(N);
        scan2<<<1, 32>>>(nb, N);
        scan3<<<nb, 1024>>>(N);
        scatter_kernel<<<histGrid, 256>>>(node_idx, hedge_idx, E);
        segagg_kernel<<<(N + 7) / 8, 256>>>(w[10], N);
        mlp_kernel<<<(N + 127) / 128, 256, 196608>>>(w[12], w[13], w[14], w[15],
                                                     w[16], w[17], out, N);
    }
}

// round 4
// speedup vs baseline: 2.8338x; 1.4252x over previous
#include <cuda_runtime.h>
#include <math.h>
#include <stdint.h>

#define IN_DIM 128
#define NHEAD 4
#define HDIM 32
#define MAX_ROWS 51200
#define MAX_E 1050000
#define SA 132   // smem stride for A/activation tiles (conflict-free frags)
#define SW 136   // smem stride for weight tiles (conflict-free B frags)

__device__ __align__(16) float g_kq[NHEAD * IN_DIM];      // [h][c]
__device__ __align__(16) float g_alpha[MAX_ROWS * NHEAD]; // [n][h]
__device__ __align__(16) float g_xv[MAX_ROWS * IN_DIM];   // [n][d*4+h]
__device__ __align__(16) float g_S1[MAX_ROWS * IN_DIM];   // pre-MLP features
__device__ __align__(16) float g_ea[MAX_E * 4];           // per CSR slot: alpha4
__device__ int g_esrc[MAX_E];                             // per CSR slot: src idx
__device__ int g_cnt[MAX_ROWS + 1];
__device__ int g_off[MAX_ROWS + 1];
__device__ int g_cur[MAX_ROWS + 1];
__device__ int g_bsum[64];

__device__ __forceinline__ float warp_sum(float v) {
    #pragma unroll
    for (int off = 16; off; off >>= 1) v += __shfl_xor_sync(0xffffffffu, v, off);
    return v;
}

__device__ __forceinline__ float to_tf32(float x) {
    uint32_t u;
    asm("cvt.rna.tf32.f32 %0, %1;" : "=r"(u) : "f"(x));
    return __uint_as_float(u);
}

__device__ __forceinline__ void mma_tile(float c[4], const uint32_t a[4],
                                         uint32_t b0, uint32_t b1) {
    asm volatile(
        "mma.sync.aligned.m16n8k8.row.col.f32.tf32.tf32.f32 "
        "{%0,%1,%2,%3}, {%4,%5,%6,%7}, {%8,%9}, {%0,%1,%2,%3};"
        : "+f"(c[0]), "+f"(c[1]), "+f"(c[2]), "+f"(c[3])
        : "r"(a[0]), "r"(a[1]), "r"(a[2]), "r"(a[3]), "r"(b0), "r"(b1));
}

// 128x128x128 GEMM: shA [128][SA] (tf32 vals), shB [128][SW] (tf32 vals).
// warp (wm 0..3, wn 0..1) computes rows wm*32..+32, cols wn*64..+64.
__device__ __forceinline__ void gemm_core(const float* __restrict__ shA,
                                          const float* __restrict__ shB,
                                          float acc[2][8][4],
                                          int wm, int wn, int lane) {
    int g = lane >> 2, t = lane & 3;
    #pragma unroll 2
    for (int k0 = 0; k0 < 128; k0 += 8) {
        uint32_t a[2][4];
        #pragma unroll
        for (int mi = 0; mi < 2; mi++) {
            const float* p = shA + (wm * 32 + mi * 16 + g) * SA + k0 + t;
            a[mi][0] = __float_as_uint(p[0]);
            a[mi][1] = __float_as_uint(p[8 * SA]);
            a[mi][2] = __float_as_uint(p[4]);
            a[mi][3] = __float_as_uint(p[8 * SA + 4]);
        }
        #pragma unroll
        for (int ni = 0; ni < 8; ni++) {
            const float* q = shB + (k0 + t) * SW + wn * 64 + ni * 8 + g;
            uint32_t b0 = __float_as_uint(q[0]);
            uint32_t b1 = __float_as_uint(q[4 * SW]);
            mma_tile(acc[0][ni], a[0], b0, b1);
            mma_tile(acc[1][ni], a[1], b0, b1);
        }
    }
}

// ---------------------------------------------------------------------------
__global__ void kq_kernel(const float* __restrict__ K, const float* __restrict__ Q) {
    int tid = threadIdx.x;
    int h = tid >> 7, c = tid & 127;
    float s = 0.f;
    #pragma unroll
    for (int d = 0; d < HDIM; d++)
        s += K[h * (IN_DIM * HDIM) + c * HDIM + d] * Q[h * HDIM + d];
    g_kq[h * IN_DIM + c] = s;
}

// alpha[n,h] = x[n] . kq[h]. one warp per row (fp32 exact for softmax).
__global__ void alpha_kernel(const float* __restrict__ x, int nrows) {
    __shared__ float kq_s[512];
    int tid = threadIdx.x;
    kq_s[tid] = g_kq[tid];
    kq_s[tid + 256] = g_kq[tid + 256];
    __syncthreads();
    int wid = tid >> 5, lane = tid & 31;
    int row = blockIdx.x * 8 + wid;
    if (row >= nrows) return;
    float4 xr = *(const float4*)&x[(size_t)row * 128 + lane * 4];
    float s[4];
    #pragma unroll
    for (int h = 0; h < 4; h++) {
        float4 k4 = *(const float4*)&kq_s[h * 128 + lane * 4];
        s[h] = warp_sum(xr.x * k4.x + xr.y * k4.y + xr.z * k4.z + xr.w * k4.w);
    }
    if (lane == 0)
        *(float4*)&g_alpha[(size_t)row * 4] = make_float4(s[0], s[1], s[2], s[3]);
}

// ---------------------------------------------------------------------------
// xv[n][d*4+h] = x @ V (cols pre-permuted). tf32 MMA.
__global__ void __launch_bounds__(256, 1)
gemm_xv(const float* __restrict__ x, const float* __restrict__ V, int nrows) {
    extern __shared__ float sm[];
    float* ws = sm;              // B: [c][d*4+h], stride SW
    float* xs = sm + 128 * SW;   // A: [r][c], stride SA (also C staging)
    int tid = threadIdx.x;
    int row0 = blockIdx.x * 128;
    int lane = tid & 31, wid = tid >> 5;
    int wm = wid & 3, wn = wid >> 2;

    for (int idx = tid; idx < 16384; idx += 256) {   // V linear: h,c,d
        int h = idx >> 12, c = (idx >> 5) & 127, d = idx & 31;
        ws[c * SW + d * 4 + h] = to_tf32(V[idx]);
    }
    for (int idx = tid; idx < 4096; idx += 256) {
        int r = idx >> 5, q = idx & 31;
        int row = row0 + r;
        float4 v = (row < nrows) ? *(const float4*)&x[(size_t)row * 128 + q * 4]
                                 : make_float4(0.f, 0.f, 0.f, 0.f);
        xs[r * SA + q * 4 + 0] = to_tf32(v.x);
        xs[r * SA + q * 4 + 1] = to_tf32(v.y);
        xs[r * SA + q * 4 + 2] = to_tf32(v.z);
        xs[r * SA + q * 4 + 3] = to_tf32(v.w);
    }
    __syncthreads();

    float acc[2][8][4];
    #pragma unroll
    for (int i = 0; i < 2; i++)
        #pragma unroll
        for (int j = 0; j < 8; j++)
            #pragma unroll
            for (int k = 0; k < 4; k++) acc[i][j][k] = 0.f;
    gemm_core(xs, ws, acc, wm, wn, lane);
    __syncthreads();

    // stage C into xs (output cols already permuted via ws layout)
    int g = lane >> 2, t = lane & 3;
    #pragma unroll
    for (int mi = 0; mi < 2; mi++)
        #pragma unroll
        for (int ni = 0; ni < 8; ni++) {
            int r = wm * 32 + mi * 16 + g;
            int c = wn * 64 + ni * 8 + 2 * t;
            *(float2*)&xs[r * SA + c] = make_float2(acc[mi][ni][0], acc[mi][ni][1]);
            *(float2*)&xs[(r + 8) * SA + c] = make_float2(acc[mi][ni][2], acc[mi][ni][3]);
        }
    __syncthreads();

    for (int idx = tid; idx < 4096; idx += 256) {
        int r = idx >> 5, q = idx & 31;
        int row = row0 + r;
        if (row < nrows)
            *(float4*)&g_xv[(size_t)row * 128 + q * 4] = *(float4*)&xs[r * SA + q * 4];
    }
}

// ---------------------------------------------------------------------------
__global__ void hist_kernel(const int* __restrict__ tgt, int E) {
    for (int e = blockIdx.x * blockDim.x + threadIdx.x; e < E;
         e += gridDim.x * blockDim.x)
        atomicAdd(&g_cnt[tgt[e]], 1);
}

__global__ void scan1(int n) {
    __shared__ int wsum[32];
    int tid = threadIdx.x, lane = tid & 31, wid = tid >> 5;
    int i = blockIdx.x * 1024 + tid;
    int v = (i < n) ? g_cnt[i] : 0;
    int x = v;
    #pragma unroll
    for (int o = 1; o < 32; o <<= 1) {
        int t = __shfl_up_sync(0xffffffffu, x, o);
        if (lane >= o) x += t;
    }
    if (lane == 31) wsum[wid] = x;
    __syncthreads();
    if (wid == 0) {
        int s = wsum[lane];
        #pragma unroll
        for (int o = 1; o < 32; o <<= 1) {
            int t = __shfl_up_sync(0xffffffffu, s, o);
            if (lane >= o) s += t;
        }
        wsum[lane] = s;
    }
    __syncthreads();
    int base = (wid > 0) ? wsum[wid - 1] : 0;
    if (i < n) g_off[i] = base + x - v;
    if (tid == 1023) g_bsum[blockIdx.x] = base + x;
}

__global__ void scan2(int nb, int n) {
    int lane = threadIdx.x;
    int v0 = (lane < nb) ? g_bsum[lane] : 0;
    int v1 = (32 + lane < nb) ? g_bsum[32 + lane] : 0;
    int x0 = v0, x1 = v1;
    #pragma unroll
    for (int o = 1; o < 32; o <<= 1) {
        int t = __shfl_up_sync(0xffffffffu, x0, o);
        if (lane >= o) x0 += t;
    }
    int tot0 = __shfl_sync(0xffffffffu, x0, 31);
    #pragma unroll
    for (int o = 1; o < 32; o <<= 1) {
        int t = __shfl_up_sync(0xffffffffu, x1, o);
        if (lane >= o) x1 += t;
    }
    x1 += tot0;
    int tot = __shfl_sync(0xffffffffu, x1, 31);
    if (lane < nb) g_bsum[lane] = x0 - v0;
    if (32 + lane < nb) g_bsum[32 + lane] = x1 - v1;
    if (lane == 0) g_off[n] = tot;
}

__global__ void scan3(int n) {
    int i = blockIdx.x * 1024 + threadIdx.x;
    if (i < n) {
        int o = g_off[i] + g_bsum[blockIdx.x];
        g_off[i] = o;
        g_cur[i] = o;
    }
}

__global__ void scatter_kernel(const int* __restrict__ tgt,
                               const int* __restrict__ src, int E) {
    for (int e = blockIdx.x * blockDim.x + threadIdx.x; e < E;
         e += gridDim.x * blockDim.x) {
        int t = tgt[e], sn = src[e];
        float4 a = *(const float4*)&g_alpha[(size_t)sn * 4];
        int p = atomicAdd(&g_cur[t], 1);
        g_esrc[p] = sn;
        *(float4*)&g_ea[(size_t)p * 4] = a;
    }
}

// ---------------------------------------------------------------------------
__global__ void segagg_kernel(const float* __restrict__ qbias, int n_tgt) {
    int gw = (int)((blockIdx.x * blockDim.x + threadIdx.x) >> 5);
    int lane = threadIdx.x & 31;
    if (gw >= n_tgt) return;
    int start = g_off[gw], end = g_off[gw + 1];
    float* outrow = &g_S1[(size_t)gw * 128];

    if (end == start) {
        #pragma unroll
        for (int k = 0; k < 4; k++) outrow[k * 32 + lane] = qbias[k * 32 + lane];
        return;
    }

    float m[4], s[4];
    #pragma unroll
    for (int k = 0; k < 4; k++) { m[k] = -1e30f; s[k] = 0.f; }
    for (int i = start + lane; i < end; i += 32) {
        float4 a4 = *(const float4*)&g_ea[(size_t)i * 4];
        float a[4] = {a4.x, a4.y, a4.z, a4.w};
        #pragma unroll
        for (int k = 0; k < 4; k++) {
            if (a[k] > m[k]) { s[k] = s[k] * __expf(m[k] - a[k]) + 1.f; m[k] = a[k]; }
            else             { s[k] += __expf(a[k] - m[k]); }
        }
    }
    #pragma unroll
    for (int off = 16; off; off >>= 1) {
        #pragma unroll
        for (int k = 0; k < 4; k++) {
            float mo = __shfl_xor_sync(0xffffffffu, m[k], off);
            float so = __shfl_xor_sync(0xffffffffu, s[k], off);
            float mn = fmaxf(m[k], mo);
            s[k] = s[k] * __expf(m[k] - mn) + so * __expf(mo - mn);
            m[k] = mn;
        }
    }
    float inv[4];
    #pragma unroll
    for (int k = 0; k < 4; k++) inv[k] = 1.0f / s[k];

    float acc[4] = {0.f, 0.f, 0.f, 0.f};
    for (int i0 = start; i0 < end; i0 += 32) {
        int cnt = end - i0; if (cnt > 32) cnt = 32;
        int idx = 0;
        float w0 = 0.f, w1 = 0.f, w2 = 0.f, w3 = 0.f;
        if (lane < cnt) {
            idx = g_esrc[i0 + lane];
            float4 a4 = *(const float4*)&g_ea[(size_t)(i0 + lane) * 4];
            w0 = __expf(a4.x - m[0]) * inv[0];
            w1 = __expf(a4.y - m[1]) * inv[1];
            w2 = __expf(a4.z - m[2]) * inv[2];
            w3 = __expf(a4.w - m[3]) * inv[3];
        }
        for (int j = 0; j < cnt; j++) {
            int sn   = __shfl_sync(0xffffffffu, idx, j);
            float a0 = __shfl_sync(0xffffffffu, w0, j);
            float a1 = __shfl_sync(0xffffffffu, w1, j);
            float a2 = __shfl_sync(0xffffffffu, w2, j);
            float a3 = __shfl_sync(0xffffffffu, w3, j);
            float4 v = *(const float4*)&g_xv[(size_t)sn * 128 + lane * 4];
            acc[0] += a0 * v.x; acc[1] += a1 * v.y;
            acc[2] += a2 * v.z; acc[3] += a3 * v.w;
        }
    }
    #pragma unroll
    for (int k = 0; k < 4; k++)
        outrow[k * 32 + lane] = acc[k] + qbias[k * 32 + lane];
}

// ---------------------------------------------------------------------------
// LN0 -> relu(h@W1) -> relu(t@W2) -> residual -> LN1 -> relu. tf32 MMA GEMMs.
__global__ void __launch_bounds__(256, 1)
mlp_kernel(const float* __restrict__ g0, const float* __restrict__ b0,
           const float* __restrict__ W1, const float* __restrict__ W2,
           const float* __restrict__ g1, const float* __restrict__ b1,
           float* __restrict__ out, int nrows) {
    extern __shared__ float sm[];
    float* sh_h = sm;                       // [128][SA] LN0 output (tf32)
    float* sh_t = sm + 128 * SA;            // [128][SA] inter / residual
    float* sh_w = sm + 256 * SA;            // [128][SW] weights (tf32)
    int tid = threadIdx.x;
    int row0 = blockIdx.x * 128;
    int wid = tid >> 5, lane = tid & 31;
    int wm = wid & 3, wn = wid >> 2;
    int g = lane >> 2, t = lane & 3;

    for (int idx = tid; idx < 4096; idx += 256) {
        int r = idx >> 5, q = idx & 31;
        int row = row0 + r;
        float4 v = (row < nrows) ? *(const float4*)&g_S1[(size_t)row * 128 + q * 4]
                                 : make_float4(0.f, 0.f, 0.f, 0.f);
        *(float4*)&sh_h[r * SA + q * 4] = v;
    }
    for (int idx = tid; idx < 4096; idx += 256) {
        float4 v = *(const float4*)&W1[idx * 4];
        int r = idx >> 5, q = idx & 31;
        sh_w[r * SW + q * 4 + 0] = to_tf32(v.x);
        sh_w[r * SW + q * 4 + 1] = to_tf32(v.y);
        sh_w[r * SW + q * 4 + 2] = to_tf32(v.z);
        sh_w[r * SW + q * 4 + 3] = to_tf32(v.w);
    }
    __syncthreads();

    // LN0 (store tf32 for GEMM1 A)
    float4 gA = *(const float4*)&g0[lane * 4];
    float4 bA = *(const float4*)&b0[lane * 4];
    for (int r = wid; r < 128; r += 8) {
        float4 v = *(float4*)&sh_h[r * SA + lane * 4];
        float mean = warp_sum(v.x + v.y + v.z + v.w) * (1.f / 128.f);
        float dx = v.x - mean, dy = v.y - mean, dz = v.z - mean, dw = v.w - mean;
        float var = warp_sum(dx * dx + dy * dy + dz * dz + dw * dw) * (1.f / 128.f);
        float rstd = rsqrtf(var + 1e-5f);
        sh_h[r * SA + lane * 4 + 0] = to_tf32(dx * rstd * gA.x + bA.x);
        sh_h[r * SA + lane * 4 + 1] = to_tf32(dy * rstd * gA.y + bA.y);
        sh_h[r * SA + lane * 4 + 2] = to_tf32(dz * rstd * gA.z + bA.z);
        sh_h[r * SA + lane * 4 + 3] = to_tf32(dw * rstd * gA.w + bA.w);
    }
    __syncthreads();

    float acc[2][8][4];
    #pragma unroll
    for (int i = 0; i < 2; i++)
        #pragma unroll
        for (int j = 0; j < 8; j++)
            #pragma unroll
            for (int k = 0; k < 4; k++) acc[i][j][k] = 0.f;
    gemm_core(sh_h, sh_w, acc, wm, wn, lane);

    // epilogue1: relu -> tf32 -> sh_t
    #pragma unroll
    for (int mi = 0; mi < 2; mi++)
        #pragma unroll
        for (int ni = 0; ni < 8; ni++) {
            int r = wm * 32 + mi * 16 + g;
            int c = wn * 64 + ni * 8 + 2 * t;
            sh_t[r * SA + c]           = to_tf32(fmaxf(acc[mi][ni][0], 0.f));
            sh_t[r * SA + c + 1]       = to_tf32(fmaxf(acc[mi][ni][1], 0.f));
            sh_t[(r + 8) * SA + c]     = to_tf32(fmaxf(acc[mi][ni][2], 0.f));
            sh_t[(r + 8) * SA + c + 1] = to_tf32(fmaxf(acc[mi][ni][3], 0.f));
        }
    __syncthreads();

    for (int idx = tid; idx < 4096; idx += 256) {
        float4 v = *(const float4*)&W2[idx * 4];
        int r = idx >> 5, q = idx & 31;
        sh_w[r * SW + q * 4 + 0] = to_tf32(v.x);
        sh_w[r * SW + q * 4 + 1] = to_tf32(v.y);
        sh_w[r * SW + q * 4 + 2] = to_tf32(v.z);
        sh_w[r * SW + q * 4 + 3] = to_tf32(v.w);
    }
    __syncthreads();

    #pragma unroll
    for (int i = 0; i < 2; i++)
        #pragma unroll
        for (int j = 0; j < 8; j++)
            #pragma unroll
            for (int k = 0; k < 4; k++) acc[i][j][k] = 0.f;
    gemm_core(sh_t, sh_w, acc, wm, wn, lane);
    __syncthreads();

    // epilogue2: residual = h + relu(m) -> sh_t (fp32)
    #pragma unroll
    for (int mi = 0; mi < 2; mi++)
        #pragma unroll
        for (int ni = 0; ni < 8; ni++) {
            int r = wm * 32 + mi * 16 + g;
            int c = wn * 64 + ni * 8 + 2 * t;
            sh_t[r * SA + c]           = sh_h[r * SA + c] + fmaxf(acc[mi][ni][0], 0.f);
            sh_t[r * SA + c + 1]       = sh_h[r * SA + c + 1] + fmaxf(acc[mi][ni][1], 0.f);
            sh_t[(r + 8) * SA + c]     = sh_h[(r + 8) * SA + c] + fmaxf(acc[mi][ni][2], 0.f);
            sh_t[(r + 8) * SA + c + 1] = sh_h[(r + 8) * SA + c + 1] + fmaxf(acc[mi][ni][3], 0.f);
        }
    __syncthreads();

    // LN1 + relu + store
    float4 gB = *(const float4*)&g1[lane * 4];
    float4 bB = *(const float4*)&b1[lane * 4];
    for (int r = wid; r < 128; r += 8) {
        float4 v = *(float4*)&sh_t[r * SA + lane * 4];
        float mean = warp_sum(v.x + v.y + v.z + v.w) * (1.f / 128.f);
        float dx = v.x - mean, dy = v.y - mean, dz = v.z - mean, dw = v.w - mean;
        float var = warp_sum(dx * dx + dy * dy + dz * dz + dw * dw) * (1.f / 128.f);
        float rstd = rsqrtf(var + 1e-5f);
        int row = row0 + r;
        if (row < nrows) {
            *(float4*)&out[(size_t)row * 128 + lane * 4] =
                make_float4(fmaxf(dx * rstd * gB.x + bB.x, 0.f),
                            fmaxf(dy * rstd * gB.y + bB.y, 0.f),
                            fmaxf(dz * rstd * gB.z + bB.z, 0.f),
                            fmaxf(dw * rstd * gB.w + bB.w, 0.f));
        }
    }
}

// ---------------------------------------------------------------------------
extern "C" void kernel_launch(void* const* d_in, const int* in_sizes, int n_in,
                              void* d_out, int out_size) {
    const int N = in_sizes[0] / IN_DIM;
    const int E = in_sizes[1];
    const int M = out_size / IN_DIM - N;

    const int wi = n_in - 18;
    const float* x0 = (const float*)d_in[0];
    const int* node_idx  = (const int*)d_in[1];
    const int* hedge_idx = (const int*)d_in[2];
    const float* w[18];
    for (int i = 0; i < 18; i++) w[i] = (const float*)d_in[wi + i];

    float* out = (float*)d_out;            // x_0_out [N,128]
    float* x1  = out + (size_t)N * IN_DIM; // x_1     [M,128]

    const int gemmSmem = (128 * SW + 128 * SA) * 4;        // ~137 KB
    const int mlpSmem  = (256 * SA + 128 * SW) * 4;        // ~205 KB
    static int s_init = 0;
    if (!s_init) {
        cudaFuncSetAttribute(gemm_xv,
                             cudaFuncAttributeMaxDynamicSharedMemorySize, gemmSmem);
        cudaFuncSetAttribute(mlp_kernel,
                             cudaFuncAttributeMaxDynamicSharedMemorySize, mlpSmem);
        s_init = 1;
    }
    void* cnt_ptr;
    cudaGetSymbolAddress(&cnt_ptr, g_cnt);

    const int histGrid = (E + 255) / 256;

    // ---- v2e: targets = hyperedges (M), sources = nodes ----
    {
        int nb = (M + 1023) / 1024;
        kq_kernel<<<1, 512>>>(w[0], w[1]);
        gemm_xv<<<(N + 127) / 128, 256, gemmSmem>>>(x0, w[2], N);
        alpha_kernel<<<(N + 7) / 8, 256>>>(x0, N);
        cudaMemsetAsync(cnt_ptr, 0, sizeof(int) * (M + 1), 0);
        hist_kernel<<<histGrid, 256>>>(hedge_idx, E);
        scan1<<<nb, 1024>>>(M);
        scan2<<<1, 32>>>(nb, M);
        scan3<<<nb, 1024>>>(M);
        scatter_kernel<<<histGrid, 256>>>(hedge_idx, node_idx, E);
        segagg_kernel<<<(M + 7) / 8, 256>>>(w[1], M);
        mlp_kernel<<<(M + 127) / 128, 256, mlpSmem>>>(w[3], w[4], w[5], w[6], w[7],
                                                      w[8], x1, M);
    }
    // ---- e2v: targets = nodes (N), sources = hyperedges ----
    {
        int nb = (N + 1023) / 1024;
        kq_kernel<<<1, 512>>>(w[9], w[10]);
        gemm_xv<<<(M + 127) / 128, 256, gemmSmem>>>(x1, w[11], M);
        alpha_kernel<<<(M + 7) / 8, 256>>>(x1, M);
        cudaMemsetAsync(cnt_ptr, 0, sizeof(int) * (N + 1), 0);
        hist_kernel<<<histGrid, 256>>>(node_idx, E);
        scan1<<<nb, 1024>>>(N);
        scan2<<<1, 32>>>(nb, N);
        scan3<<<nb, 1024>>>(N);
        scatter_kernel<<<histGrid, 256>>>(node_idx, hedge_idx, E);
        segagg_kernel<<<(N + 7) / 8, 256>>>(w[10], N);
        mlp_kernel<<<(N + 127) / 128, 256, mlpSmem>>>(w[12], w[13], w[14], w[15],
                                                      w[16], w[17], out, N);
    }
}

// round 5
// speedup vs baseline: 3.3032x; 1.1656x over previous
#include <cuda_runtime.h>
#include <math.h>
#include <stdint.h>

#define IN_DIM 128
#define NHEAD 4
#define HDIM 32
#define MAX_ROWS 51200
#define MAX_E 1050000
#define SA 132   // smem stride for A/activation tiles
#define SW 136   // smem stride for weight tiles

__device__ __align__(16) float g_kq[NHEAD * IN_DIM];      // [h][c]
__device__ __align__(16) float g_alpha[MAX_ROWS * NHEAD]; // [n][h]
__device__ __align__(16) float g_xv[MAX_ROWS * IN_DIM];   // [n][d*4+h]
__device__ __align__(16) float g_S1[MAX_ROWS * IN_DIM];   // pre-MLP features
__device__ int g_esrcA[MAX_E];
__device__ int g_esrcB[MAX_E];
__device__ int g_offA[MAX_ROWS + 1];
__device__ int g_offB[MAX_ROWS + 1];
__device__ int g_cnt[MAX_ROWS + 1];
__device__ int g_cur[MAX_ROWS + 1];
__device__ int g_bsum[64];

__device__ __forceinline__ float warp_sum(float v) {
    #pragma unroll
    for (int off = 16; off; off >>= 1) v += __shfl_xor_sync(0xffffffffu, v, off);
    return v;
}

__device__ __forceinline__ float to_tf32(float x) {
    uint32_t u;
    asm("cvt.rna.tf32.f32 %0, %1;" : "=r"(u) : "f"(x));
    return __uint_as_float(u);
}

__device__ __forceinline__ void mma_tile(float c[4], const uint32_t a[4],
                                         uint32_t b0, uint32_t b1) {
    asm volatile(
        "mma.sync.aligned.m16n8k8.row.col.f32.tf32.tf32.f32 "
        "{%0,%1,%2,%3}, {%4,%5,%6,%7}, {%8,%9}, {%0,%1,%2,%3};"
        : "+f"(c[0]), "+f"(c[1]), "+f"(c[2]), "+f"(c[3])
        : "r"(a[0]), "r"(a[1]), "r"(a[2]), "r"(a[3]), "r"(b0), "r"(b1));
}

// 128x128x128 GEMM on smem tiles. warp (wm 0..3, wn 0..1).
__device__ __forceinline__ void gemm_core(const float* __restrict__ shA,
                                          const float* __restrict__ shB,
                                          float acc[2][8][4],
                                          int wm, int wn, int lane) {
    int g = lane >> 2, t = lane & 3;
    #pragma unroll 2
    for (int k0 = 0; k0 < 128; k0 += 8) {
        uint32_t a[2][4];
        #pragma unroll
        for (int mi = 0; mi < 2; mi++) {
            const float* p = shA + (wm * 32 + mi * 16 + g) * SA + k0 + t;
            a[mi][0] = __float_as_uint(p[0]);
            a[mi][1] = __float_as_uint(p[8 * SA]);
            a[mi][2] = __float_as_uint(p[4]);
            a[mi][3] = __float_as_uint(p[8 * SA + 4]);
        }
        #pragma unroll
        for (int ni = 0; ni < 8; ni++) {
            const float* q = shB + (k0 + t) * SW + wn * 64 + ni * 8 + g;
            uint32_t b0 = __float_as_uint(q[0]);
            uint32_t b1 = __float_as_uint(q[4 * SW]);
            mma_tile(acc[0][ni], a[0], b0, b1);
            mma_tile(acc[1][ni], a[1], b0, b1);
        }
    }
}

// ---------------------------------------------------------------------------
__global__ void kq_kernel(const float* __restrict__ K, const float* __restrict__ Q) {
    int tid = threadIdx.x;
    int h = tid >> 7, c = tid & 127;
    float s = 0.f;
    #pragma unroll
    for (int d = 0; d < HDIM; d++)
        s += K[h * (IN_DIM * HDIM) + c * HDIM + d] * Q[h * HDIM + d];
    g_kq[h * IN_DIM + c] = s;
}

__global__ void alpha_kernel(const float* __restrict__ x, int nrows) {
    __shared__ float kq_s[512];
    int tid = threadIdx.x;
    kq_s[tid] = g_kq[tid];
    kq_s[tid + 256] = g_kq[tid + 256];
    __syncthreads();
    int wid = tid >> 5, lane = tid & 31;
    int row = blockIdx.x * 8 + wid;
    if (row >= nrows) return;
    float4 xr = *(const float4*)&x[(size_t)row * 128 + lane * 4];
    float s[4];
    #pragma unroll
    for (int h = 0; h < 4; h++) {
        float4 k4 = *(const float4*)&kq_s[h * 128 + lane * 4];
        s[h] = warp_sum(xr.x * k4.x + xr.y * k4.y + xr.z * k4.z + xr.w * k4.w);
    }
    if (lane == 0)
        *(float4*)&g_alpha[(size_t)row * 4] = make_float4(s[0], s[1], s[2], s[3]);
}

// ---------------------------------------------------------------------------
__global__ void __launch_bounds__(256, 1)
gemm_xv(const float* __restrict__ x, const float* __restrict__ V, int nrows) {
    extern __shared__ float sm[];
    float* ws = sm;              // B: [c][d*4+h], stride SW
    float* xs = sm + 128 * SW;   // A: [r][c], stride SA (also C staging)
    int tid = threadIdx.x;
    int row0 = blockIdx.x * 128;
    int lane = tid & 31, wid = tid >> 5;
    int wm = wid & 3, wn = wid >> 2;

    for (int idx = tid; idx < 16384; idx += 256) {   // V linear: h,c,d
        int h = idx >> 12, c = (idx >> 5) & 127, d = idx & 31;
        ws[c * SW + d * 4 + h] = to_tf32(V[idx]);
    }
    for (int idx = tid; idx < 4096; idx += 256) {
        int r = idx >> 5, q = idx & 31;
        int row = row0 + r;
        float4 v = (row < nrows) ? *(const float4*)&x[(size_t)row * 128 + q * 4]
                                 : make_float4(0.f, 0.f, 0.f, 0.f);
        xs[r * SA + q * 4 + 0] = to_tf32(v.x);
        xs[r * SA + q * 4 + 1] = to_tf32(v.y);
        xs[r * SA + q * 4 + 2] = to_tf32(v.z);
        xs[r * SA + q * 4 + 3] = to_tf32(v.w);
    }
    __syncthreads();

    float acc[2][8][4];
    #pragma unroll
    for (int i = 0; i < 2; i++)
        #pragma unroll
        for (int j = 0; j < 8; j++)
            #pragma unroll
            for (int k = 0; k < 4; k++) acc[i][j][k] = 0.f;
    gemm_core(xs, ws, acc, wm, wn, lane);
    __syncthreads();

    int g = lane >> 2, t = lane & 3;
    #pragma unroll
    for (int mi = 0; mi < 2; mi++)
        #pragma unroll
        for (int ni = 0; ni < 8; ni++) {
            int r = wm * 32 + mi * 16 + g;
            int c = wn * 64 + ni * 8 + 2 * t;
            *(float2*)&xs[r * SA + c] = make_float2(acc[mi][ni][0], acc[mi][ni][1]);
            *(float2*)&xs[(r + 8) * SA + c] = make_float2(acc[mi][ni][2], acc[mi][ni][3]);
        }
    __syncthreads();

    for (int idx = tid; idx < 4096; idx += 256) {
        int r = idx >> 5, q = idx & 31;
        int row = row0 + r;
        if (row < nrows)
            *(float4*)&g_xv[(size_t)row * 128 + q * 4] = *(float4*)&xs[r * SA + q * 4];
    }
}

// ---------------------------------------------------------------------------
__global__ void hist_kernel(const int* __restrict__ tgt, int E) {
    for (int e = blockIdx.x * blockDim.x + threadIdx.x; e < E;
         e += gridDim.x * blockDim.x)
        atomicAdd(&g_cnt[tgt[e]], 1);
}

__global__ void scan1(int n, int* __restrict__ off) {
    __shared__ int wsum[32];
    int tid = threadIdx.x, lane = tid & 31, wid = tid >> 5;
    int i = blockIdx.x * 1024 + tid;
    int v = (i < n) ? g_cnt[i] : 0;
    int x = v;
    #pragma unroll
    for (int o = 1; o < 32; o <<= 1) {
        int t = __shfl_up_sync(0xffffffffu, x, o);
        if (lane >= o) x += t;
    }
    if (lane == 31) wsum[wid] = x;
    __syncthreads();
    if (wid == 0) {
        int s = wsum[lane];
        #pragma unroll
        for (int o = 1; o < 32; o <<= 1) {
            int t = __shfl_up_sync(0xffffffffu, s, o);
            if (lane >= o) s += t;
        }
        wsum[lane] = s;
    }
    __syncthreads();
    int base = (wid > 0) ? wsum[wid - 1] : 0;
    if (i < n) off[i] = base + x - v;
    if (tid == 1023) g_bsum[blockIdx.x] = base + x;
}

__global__ void scan2(int nb, int n, int* __restrict__ off) {
    int lane = threadIdx.x;
    int v0 = (lane < nb) ? g_bsum[lane] : 0;
    int v1 = (32 + lane < nb) ? g_bsum[32 + lane] : 0;
    int x0 = v0, x1 = v1;
    #pragma unroll
    for (int o = 1; o < 32; o <<= 1) {
        int t = __shfl_up_sync(0xffffffffu, x0, o);
        if (lane >= o) x0 += t;
    }
    int tot0 = __shfl_sync(0xffffffffu, x0, 31);
    #pragma unroll
    for (int o = 1; o < 32; o <<= 1) {
        int t = __shfl_up_sync(0xffffffffu, x1, o);
        if (lane >= o) x1 += t;
    }
    x1 += tot0;
    int tot = __shfl_sync(0xffffffffu, x1, 31);
    if (lane < nb) g_bsum[lane] = x0 - v0;
    if (32 + lane < nb) g_bsum[32 + lane] = x1 - v1;
    if (lane == 0) off[n] = tot;
}

__global__ void scan3(int n, int* __restrict__ off) {
    int i = blockIdx.x * 1024 + threadIdx.x;
    if (i < n) {
        int o = off[i] + g_bsum[blockIdx.x];
        off[i] = o;
        g_cur[i] = o;
    }
}

// topology-only scatter: CSR slot <- source index
__global__ void scatter_kernel(const int* __restrict__ tgt,
                               const int* __restrict__ src,
                               int* __restrict__ esrc, int E) {
    for (int e = blockIdx.x * blockDim.x + threadIdx.x; e < E;
         e += gridDim.x * blockDim.x) {
        int p = atomicAdd(&g_cur[tgt[e]], 1);
        esrc[p] = src[e];
    }
}

// ---------------------------------------------------------------------------
// One warp per target. pass1: online softmax over gathered alpha.
// pass2: stage (idx, w4) in smem, broadcast via LDS, one float4 gather/edge.
__global__ void __launch_bounds__(256)
segagg_kernel(const int* __restrict__ esrc, const int* __restrict__ off,
              const float* __restrict__ qbias, int n_tgt) {
    __shared__ int   sh_sn[256];
    __shared__ float4 sh_w[256];
    int wid = threadIdx.x >> 5, lane = threadIdx.x & 31;
    int gw = blockIdx.x * 8 + wid;
    if (gw >= n_tgt) return;
    int start = off[gw], end = off[gw + 1];
    float* outrow = &g_S1[(size_t)gw * 128];

    if (end == start) {
        #pragma unroll
        for (int k = 0; k < 4; k++) outrow[k * 32 + lane] = qbias[k * 32 + lane];
        return;
    }

    float m[4], s[4];
    #pragma unroll
    for (int k = 0; k < 4; k++) { m[k] = -1e30f; s[k] = 0.f; }
    for (int i = start + lane; i < end; i += 32) {
        int sn = __ldg(&esrc[i]);
        float4 a4 = *(const float4*)&g_alpha[(size_t)sn * 4];
        float a[4] = {a4.x, a4.y, a4.z, a4.w};
        #pragma unroll
        for (int k = 0; k < 4; k++) {
            if (a[k] > m[k]) { s[k] = s[k] * __expf(m[k] - a[k]) + 1.f; m[k] = a[k]; }
            else             { s[k] += __expf(a[k] - m[k]); }
        }
    }
    #pragma unroll
    for (int offx = 16; offx; offx >>= 1) {
        #pragma unroll
        for (int k = 0; k < 4; k++) {
            float mo = __shfl_xor_sync(0xffffffffu, m[k], offx);
            float so = __shfl_xor_sync(0xffffffffu, s[k], offx);
            float mn = fmaxf(m[k], mo);
            s[k] = s[k] * __expf(m[k] - mn) + so * __expf(mo - mn);
            m[k] = mn;
        }
    }
    float inv[4];
    #pragma unroll
    for (int k = 0; k < 4; k++) inv[k] = 1.0f / s[k];

    int sbase = wid * 32;
    float acc[4] = {0.f, 0.f, 0.f, 0.f};
    for (int i0 = start; i0 < end; i0 += 32) {
        int cnt = end - i0; if (cnt > 32) cnt = 32;
        if (lane < cnt) {
            int sn = __ldg(&esrc[i0 + lane]);
            float4 a4 = *(const float4*)&g_alpha[(size_t)sn * 4];
            sh_sn[sbase + lane] = sn;
            sh_w[sbase + lane] = make_float4(__expf(a4.x - m[0]) * inv[0],
                                            __expf(a4.y - m[1]) * inv[1],
                                            __expf(a4.z - m[2]) * inv[2],
                                            __expf(a4.w - m[3]) * inv[3]);
        }
        __syncwarp();
        #pragma unroll 4
        for (int j = 0; j < cnt; j++) {
            int sn = sh_sn[sbase + j];
            float4 wv = sh_w[sbase + j];
            float4 v = *(const float4*)&g_xv[(size_t)sn * 128 + lane * 4];
            acc[0] += wv.x * v.x; acc[1] += wv.y * v.y;
            acc[2] += wv.z * v.z; acc[3] += wv.w * v.w;
        }
        __syncwarp();
    }
    #pragma unroll
    for (int k = 0; k < 4; k++)
        outrow[k * 32 + lane] = acc[k] + qbias[k * 32 + lane];
}

// ---------------------------------------------------------------------------
__global__ void __launch_bounds__(256, 1)
mlp_kernel(const float* __restrict__ g0, const float* __restrict__ b0,
           const float* __restrict__ W1, const float* __restrict__ W2,
           const float* __restrict__ g1, const float* __restrict__ b1,
           float* __restrict__ out, int nrows) {
    extern __shared__ float sm[];
    float* sh_h = sm;                       // [128][SA]
    float* sh_t = sm + 128 * SA;            // [128][SA]
    float* sh_w = sm + 256 * SA;            // [128][SW]
    int tid = threadIdx.x;
    int row0 = blockIdx.x * 128;
    int wid = tid >> 5, lane = tid & 31;
    int wm = wid & 3, wn = wid >> 2;
    int g = lane >> 2, t = lane & 3;

    for (int idx = tid; idx < 4096; idx += 256) {
        int r = idx >> 5, q = idx & 31;
        int row = row0 + r;
        float4 v = (row < nrows) ? *(const float4*)&g_S1[(size_t)row * 128 + q * 4]
                                 : make_float4(0.f, 0.f, 0.f, 0.f);
        *(float4*)&sh_h[r * SA + q * 4] = v;
    }
    for (int idx = tid; idx < 4096; idx += 256) {
        float4 v = *(const float4*)&W1[idx * 4];
        int r = idx >> 5, q = idx & 31;
        sh_w[r * SW + q * 4 + 0] = to_tf32(v.x);
        sh_w[r * SW + q * 4 + 1] = to_tf32(v.y);
        sh_w[r * SW + q * 4 + 2] = to_tf32(v.z);
        sh_w[r * SW + q * 4 + 3] = to_tf32(v.w);
    }
    __syncthreads();

    float4 gA = *(const float4*)&g0[lane * 4];
    float4 bA = *(const float4*)&b0[lane * 4];
    for (int r = wid; r < 128; r += 8) {
        float4 v = *(float4*)&sh_h[r * SA + lane * 4];
        float mean = warp_sum(v.x + v.y + v.z + v.w) * (1.f / 128.f);
        float dx = v.x - mean, dy = v.y - mean, dz = v.z - mean, dw = v.w - mean;
        float var = warp_sum(dx * dx + dy * dy + dz * dz + dw * dw) * (1.f / 128.f);
        float rstd = rsqrtf(var + 1e-5f);
        sh_h[r * SA + lane * 4 + 0] = to_tf32(dx * rstd * gA.x + bA.x);
        sh_h[r * SA + lane * 4 + 1] = to_tf32(dy * rstd * gA.y + bA.y);
        sh_h[r * SA + lane * 4 + 2] = to_tf32(dz * rstd * gA.z + bA.z);
        sh_h[r * SA + lane * 4 + 3] = to_tf32(dw * rstd * gA.w + bA.w);
    }
    __syncthreads();

    float acc[2][8][4];
    #pragma unroll
    for (int i = 0; i < 2; i++)
        #pragma unroll
        for (int j = 0; j < 8; j++)
            #pragma unroll
            for (int k = 0; k < 4; k++) acc[i][j][k] = 0.f;
    gemm_core(sh_h, sh_w, acc, wm, wn, lane);

    #pragma unroll
    for (int mi = 0; mi < 2; mi++)
        #pragma unroll
        for (int ni = 0; ni < 8; ni++) {
            int r = wm * 32 + mi * 16 + g;
            int c = wn * 64 + ni * 8 + 2 * t;
            sh_t[r * SA + c]           = to_tf32(fmaxf(acc[mi][ni][0], 0.f));
            sh_t[r * SA + c + 1]       = to_tf32(fmaxf(acc[mi][ni][1], 0.f));
            sh_t[(r + 8) * SA + c]     = to_tf32(fmaxf(acc[mi][ni][2], 0.f));
            sh_t[(r + 8) * SA + c + 1] = to_tf32(fmaxf(acc[mi][ni][3], 0.f));
        }
    __syncthreads();

    for (int idx = tid; idx < 4096; idx += 256) {
        float4 v = *(const float4*)&W2[idx * 4];
        int r = idx >> 5, q = idx & 31;
        sh_w[r * SW + q * 4 + 0] = to_tf32(v.x);
        sh_w[r * SW + q * 4 + 1] = to_tf32(v.y);
        sh_w[r * SW + q * 4 + 2] = to_tf32(v.z);
        sh_w[r * SW + q * 4 + 3] = to_tf32(v.w);
    }
    __syncthreads();

    #pragma unroll
    for (int i = 0; i < 2; i++)
        #pragma unroll
        for (int j = 0; j < 8; j++)
            #pragma unroll
            for (int k = 0; k < 4; k++) acc[i][j][k] = 0.f;
    gemm_core(sh_t, sh_w, acc, wm, wn, lane);
    __syncthreads();

    #pragma unroll
    for (int mi = 0; mi < 2; mi++)
        #pragma unroll
        for (int ni = 0; ni < 8; ni++) {
            int r = wm * 32 + mi * 16 + g;
            int c = wn * 64 + ni * 8 + 2 * t;
            sh_t[r * SA + c]           = sh_h[r * SA + c] + fmaxf(acc[mi][ni][0], 0.f);
            sh_t[r * SA + c + 1]       = sh_h[r * SA + c + 1] + fmaxf(acc[mi][ni][1], 0.f);
            sh_t[(r + 8) * SA + c]     = sh_h[(r + 8) * SA + c] + fmaxf(acc[mi][ni][2], 0.f);
            sh_t[(r + 8) * SA + c + 1] = sh_h[(r + 8) * SA + c + 1] + fmaxf(acc[mi][ni][3], 0.f);
        }
    __syncthreads();

    float4 gB = *(const float4*)&g1[lane * 4];
    float4 bB = *(const float4*)&b1[lane * 4];
    for (int r = wid; r < 128; r += 8) {
        float4 v = *(float4*)&sh_t[r * SA + lane * 4];
        float mean = warp_sum(v.x + v.y + v.z + v.w) * (1.f / 128.f);
        float dx = v.x - mean, dy = v.y - mean, dz = v.z - mean, dw = v.w - mean;
        float var = warp_sum(dx * dx + dy * dy + dz * dz + dw * dw) * (1.f / 128.f);
        float rstd = rsqrtf(var + 1e-5f);
        int row = row0 + r;
        if (row < nrows) {
            *(float4*)&out[(size_t)row * 128 + lane * 4] =
                make_float4(fmaxf(dx * rstd * gB.x + bB.x, 0.f),
                            fmaxf(dy * rstd * gB.y + bB.y, 0.f),
                            fmaxf(dz * rstd * gB.z + bB.z, 0.f),
                            fmaxf(dw * rstd * gB.w + bB.w, 0.f));
        }
    }
}

// ---------------------------------------------------------------------------
extern "C" void kernel_launch(void* const* d_in, const int* in_sizes, int n_in,
                              void* d_out, int out_size) {
    const int N = in_sizes[0] / IN_DIM;
    const int E = in_sizes[1];
    const int M = out_size / IN_DIM - N;

    const int wi = n_in - 18;
    const float* x0 = (const float*)d_in[0];
    const int* node_idx  = (const int*)d_in[1];
    const int* hedge_idx = (const int*)d_in[2];
    const float* w[18];
    for (int i = 0; i < 18; i++) w[i] = (const float*)d_in[wi + i];

    float* out = (float*)d_out;            // x_0_out [N,128]
    float* x1  = out + (size_t)N * IN_DIM; // x_1     [M,128]

    const int gemmSmem = (128 * SW + 128 * SA) * 4;
    const int mlpSmem  = (256 * SA + 128 * SW) * 4;

    static int s_init = 0;
    static cudaStream_t s2;
    static cudaEvent_t evFork, evA, evB;
    static void *cnt_ptr, *offA_ptr, *offB_ptr, *esrcA_ptr, *esrcB_ptr;
    if (!s_init) {
        cudaFuncSetAttribute(gemm_xv,
                             cudaFuncAttributeMaxDynamicSharedMemorySize, gemmSmem);
        cudaFuncSetAttribute(mlp_kernel,
                             cudaFuncAttributeMaxDynamicSharedMemorySize, mlpSmem);
        cudaStreamCreateWithFlags(&s2, cudaStreamNonBlocking);
        cudaEventCreateWithFlags(&evFork, cudaEventDisableTiming);
        cudaEventCreateWithFlags(&evA, cudaEventDisableTiming);
        cudaEventCreateWithFlags(&evB, cudaEventDisableTiming);
        cudaGetSymbolAddress(&cnt_ptr, g_cnt);
        cudaGetSymbolAddress(&offA_ptr, g_offA);
        cudaGetSymbolAddress(&offB_ptr, g_offB);
        cudaGetSymbolAddress(&esrcA_ptr, g_esrcA);
        cudaGetSymbolAddress(&esrcB_ptr, g_esrcB);
        s_init = 1;
    }
    int* offA = (int*)offA_ptr;
    int* offB = (int*)offB_ptr;
    int* esrcA = (int*)esrcA_ptr;
    int* esrcB = (int*)esrcB_ptr;

    const int histGrid = (E + 255) / 256;
    const int nbM = (M + 1023) / 1024, nbN = (N + 1023) / 1024;

    // fork: CSR builds (topology-only) on s2, concurrent with compute
    cudaEventRecord(evFork, 0);
    cudaStreamWaitEvent(s2, evFork, 0);

    // s2: CSR A (targets = hyperedges)
    cudaMemsetAsync(cnt_ptr, 0, sizeof(int) * (M + 1), s2);
    hist_kernel<<<histGrid, 256, 0, s2>>>(hedge_idx, E);
    scan1<<<nbM, 1024, 0, s2>>>(M, offA);
    scan2<<<1, 32, 0, s2>>>(nbM, M, offA);
    scan3<<<nbM, 1024, 0, s2>>>(M, offA);
    scatter_kernel<<<histGrid, 256, 0, s2>>>(hedge_idx, node_idx, esrcA, E);
    cudaEventRecord(evA, s2);
    // s2: CSR B (targets = nodes)
    cudaMemsetAsync(cnt_ptr, 0, sizeof(int) * (N + 1), s2);
    hist_kernel<<<histGrid, 256, 0, s2>>>(node_idx, E);
    scan1<<<nbN, 1024, 0, s2>>>(N, offB);
    scan2<<<1, 32, 0, s2>>>(nbN, N, offB);
    scan3<<<nbN, 1024, 0, s2>>>(N, offB);
    scatter_kernel<<<histGrid, 256, 0, s2>>>(node_idx, hedge_idx, esrcB, E);
    cudaEventRecord(evB, s2);

    // stream 0: phase 1 (v2e)
    kq_kernel<<<1, 512>>>(w[0], w[1]);
    gemm_xv<<<(N + 127) / 128, 256, gemmSmem>>>(x0, w[2], N);
    alpha_kernel<<<(N + 7) / 8, 256>>>(x0, N);
    cudaStreamWaitEvent(0, evA, 0);
    segagg_kernel<<<(M + 7) / 8, 256>>>(esrcA, offA, w[1], M);
    mlp_kernel<<<(M + 127) / 128, 256, mlpSmem>>>(w[3], w[4], w[5], w[6], w[7],
                                                  w[8], x1, M);
    // phase 2 (e2v)
    kq_kernel<<<1, 512>>>(w[9], w[10]);
    gemm_xv<<<(M + 127) / 128, 256, gemmSmem>>>(x1, w[11], M);
    alpha_kernel<<<(M + 7) / 8, 256>>>(x1, M);
    cudaStreamWaitEvent(0, evB, 0);
    segagg_kernel<<<(N + 7) / 8, 256>>>(esrcB, offB, w[10], N);
    mlp_kernel<<<(N + 127) / 128, 256, mlpSmem>>>(w[12], w[13], w[14], w[15],
                                                  w[16], w[17], out, N);
}